// round 13
// baseline (speedup 1.0000x reference)
#include <cuda_runtime.h>
#include <cuda_fp16.h>
#include <cstdint>

#define BB 128
#define TT 64
#define II 196
#define DD 512

// ---------------- scratch --------------------------------------------------
__device__ __align__(16) __half g_txt[BB * TT * DD];
__device__ __align__(16) __half g_img[BB * II * DD];
__device__ float g_S[BB * BB];

// ---------------- stage layout (bytes); K-chunk = 64 halves = 128 B/row ----
// A: 64 rows x 128B = 8192 ; B: 208 rows x 128B = 26624
#define A_T  0
#define B_T  8192
#define STAGE_SZ 34816
#define N_STAGE 3
#define SMEM_TOTAL (N_STAGE * STAGE_SZ + 2048)   // 106496 -> 2 CTAs/SM

// ---------------- PTX helpers ----------------------------------------------
__device__ __forceinline__ uint32_t smem_u32(const void* p) {
    uint32_t a;
    asm("{ .reg .u64 t; cvta.to.shared.u64 t, %1; cvt.u32.u64 %0, t; }"
        : "=r"(a) : "l"(p));
    return a;
}
__device__ __forceinline__ void cp16(uint32_t dst, const void* src) {
    asm volatile("cp.async.cg.shared.global [%0], [%1], 16;"
                 :: "r"(dst), "l"(src) : "memory");
}
#define CP_COMMIT() asm volatile("cp.async.commit_group;" ::: "memory")
#define CP_WAIT2()  asm volatile("cp.async.wait_group 2;" ::: "memory")
#define CP_WAIT1()  asm volatile("cp.async.wait_group 1;" ::: "memory")
#define CP_WAIT0()  asm volatile("cp.async.wait_group 0;" ::: "memory")

__device__ __forceinline__ void ldsm4(uint32_t* r, uint32_t addr) {
    asm volatile("ldmatrix.sync.aligned.m8n8.x4.shared.b16 {%0,%1,%2,%3}, [%4];"
                 : "=r"(r[0]), "=r"(r[1]), "=r"(r[2]), "=r"(r[3]) : "r"(addr));
}
__device__ __forceinline__ void mma_f16(float* c, const uint32_t* a, const uint32_t* b) {
    asm volatile("mma.sync.aligned.m16n8k16.row.col.f32.f16.f16.f32 "
                 "{%0,%1,%2,%3}, {%4,%5,%6,%7}, {%8,%9}, {%0,%1,%2,%3};"
                 : "+f"(c[0]), "+f"(c[1]), "+f"(c[2]), "+f"(c[3])
                 : "r"(a[0]), "r"(a[1]), "r"(a[2]), "r"(a[3]),
                   "r"(b[0]), "r"(b[1]));
}
__device__ __forceinline__ uint32_t swz(int row, uint32_t kb) {
    return (uint32_t)row * 128u + (kb ^ (uint32_t)((row & 7) << 4));
}

// ---------------- fused round kernel: fp32 -> fp16 (both tensors) -----------
__global__ __launch_bounds__(256)
void round2_kernel(const float* __restrict__ t, const float* __restrict__ im,
                   __half* __restrict__ th, __half* __restrict__ ih,
                   int nt4, int ni4)
{
    int i = blockIdx.x * 256 + threadIdx.x;
    const float* src;
    __half* dst;
    int j;
    if (i < nt4)       { src = t;  dst = th; j = i; }
    else               { j = i - nt4; if (j >= ni4) return; src = im; dst = ih; }
    float4 v = reinterpret_cast<const float4*>(src)[j];
    __half2 a(__float2half(v.x), __float2half(v.y));
    __half2 b(__float2half(v.z), __float2half(v.w));
    uint2 u;
    u.x = *(uint32_t*)&a; u.y = *(uint32_t*)&b;
    reinterpret_cast<uint2*>(dst)[j] = u;
}

// ---------------- stage loader (128 threads) --------------------------------
__device__ __forceinline__ void issue_stage(uint32_t sb,
    const __half* At, const __half* Bt, int k0, int tid)
{
    #pragma unroll
    for (int q = 0; q < 4; q++) {                 // A: 64 rows x 8 segs(16B)
        int u = tid + q * 128;
        int row = u >> 3, seg = u & 7;
        uint32_t o = swz(row, seg * 16);
        size_t g = (size_t)row * DD + k0 + seg * 8;
        cp16(sb + A_T + o, At + g);
    }
    #pragma unroll
    for (int q = 0; q < 13; q++) {                // B: 196 rows x 8 segs = 1568
        int u = tid + q * 128;
        if (u < II * 8) {
            int row = u >> 3, seg = u & 7;
            uint32_t o = swz(row, seg * 16);
            size_t g = (size_t)row * DD + k0 + seg * 8;
            cp16(sb + B_T + o, Bt + g);
        }
    }
}

// ---------------- per-chunk compute: m16 x n200 warp tile (uniform) ---------
__device__ __forceinline__ void compute_chunk(uint32_t sb, float* c,
                                              int wid, int lane)
{
    const int rowA0 = wid * 16 + (lane & 15);
    const uint32_t kAh = (lane & 16) ? 16u : 0u;
    const int rowB0 = ((lane & 16) ? 8 : 0) + (lane & 7);
    const uint32_t kBh = (lane & 8) ? 16u : 0u;

    #pragma unroll
    for (int s = 0; s < 4; s++) {
        uint32_t a[4];
        {
            uint32_t o = swz(rowA0, s * 32 + kAh);
            ldsm4(a, sb + A_T + o);
        }
        uint32_t b[52];
        #pragma unroll
        for (int p = 0; p < 13; p++) {            // rows p*16 .. p*16+15 (<208)
            uint32_t o = swz(rowB0 + p * 16, s * 32 + kBh);
            ldsm4(b + 4 * p, sb + B_T + o);
        }
        #pragma unroll
        for (int nt = 0; nt < 25; nt++)
            mma_f16(c + nt * 4, a, b + 2 * nt);
    }
}

// ---------------- main maxsim kernel ----------------------------------------
__global__ __launch_bounds__(128, 2)
void maxsim_mma_kernel()
{
    extern __shared__ __align__(1024) char smem[];
    const uint32_t sb = smem_u32(smem);
    const int tid  = threadIdx.x;
    const int lane = tid & 31;
    const int wid  = tid >> 5;      // 0..3 : M strip of 16

    const int b1 = blockIdx.x;      // text batch
    const int b2 = blockIdx.y;      // image batch
    const __half* At = g_txt + (size_t)b1 * (TT * DD);
    const __half* Bt = g_img + (size_t)b2 * (II * DD);

    // zero B pad rows (196..207) in all stages
    {
        uint4 z = make_uint4(0, 0, 0, 0);
        for (int u = tid; u < 12 * 8 * N_STAGE; u += 128) {
            int st = u / 96, v = u % 96;
            int row = 196 + (v >> 3), seg = v & 7;
            uint32_t o = swz(row, seg * 16);
            *(uint4*)(smem + st * STAGE_SZ + B_T + o) = z;
        }
    }
    __syncthreads();

    issue_stage(sb,                At, Bt, 0,   tid); CP_COMMIT();
    issue_stage(sb + STAGE_SZ,     At, Bt, 64,  tid); CP_COMMIT();
    issue_stage(sb + 2 * STAGE_SZ, At, Bt, 128, tid); CP_COMMIT();

    float c[100];
    #pragma unroll
    for (int i = 0; i < 100; i++) c[i] = 0.0f;

    #pragma unroll 1
    for (int ck = 0; ck < 8; ck++) {
        if (ck < 6) CP_WAIT2();
        else if (ck == 6) CP_WAIT1();
        else CP_WAIT0();
        __syncthreads();
        const uint32_t stg = sb + (uint32_t)(ck % 3) * STAGE_SZ;
        compute_chunk(stg, c, wid, lane);
        __syncthreads();
        if (ck + 3 <= 7) {
            issue_stage(stg, At, Bt, (ck + 3) * 64, tid);
            CP_COMMIT();
        }
    }

    // ---------------- epilogue: masked row-max, then mean over tokens -------
    // lane quad layout: rows r0 = lane>>2 and r0+8; cols nt*8 + 2*(lane&3)+{0,1}
    float* red = (float*)smem;      // [64]
    float m0 = -3.0e38f, m1 = -3.0e38f;
    #pragma unroll
    for (int nt = 0; nt < 24; nt++) {             // i <= 191: unmasked
        const float* acc = c + nt * 4;
        m0 = fmaxf(m0, fmaxf(acc[0], acc[1]));
        m1 = fmaxf(m1, fmaxf(acc[2], acc[3]));
    }
    {   // nt = 24: i0 = 192 + 2*(lane&3); mask i >= 196
        const float* acc = c + 24 * 4;
        int i0 = 192 + 2 * (lane & 3);
        if (i0 < II)     { m0 = fmaxf(m0, acc[0]); m1 = fmaxf(m1, acc[2]); }
        if (i0 + 1 < II) { m0 = fmaxf(m0, acc[1]); m1 = fmaxf(m1, acc[3]); }
    }
    #pragma unroll
    for (int o = 1; o <= 2; o <<= 1) {
        m0 = fmaxf(m0, __shfl_xor_sync(0xffffffffu, m0, o));
        m1 = fmaxf(m1, __shfl_xor_sync(0xffffffffu, m1, o));
    }
    if ((lane & 3) == 0) {
        int t = wid * 16 + (lane >> 2);
        red[t]     = m0;
        red[t + 8] = m1;
    }
    __syncthreads();
    if (wid == 0) {
        float v = red[lane] + red[lane + 32];
        #pragma unroll
        for (int o = 16; o >= 1; o >>= 1) v += __shfl_xor_sync(0xffffffffu, v, o);
        if (lane == 0) g_S[b1 * BB + b2] = v * (1.0f / 64.0f);
    }
}

// ---------------- loss kernel (1024 thr; 4 lanes per row/col) ---------------
__global__ __launch_bounds__(1024)
void loss_kernel(float* __restrict__ out)
{
    extern __shared__ float sh[];                 // [128][129]
    __shared__ float ws[32];
    const int tid = threadIdx.x;
    const float invT = 1.0f / 0.07f;

    for (int i = tid; i < BB * 32; i += 1024) {
        int b = i >> 5, j4 = i & 31;
        float4 v = reinterpret_cast<const float4*>(g_S)[b * 32 + j4];
        float* row = sh + b * 129 + j4 * 4;
        row[0] = v.x; row[1] = v.y; row[2] = v.z; row[3] = v.w;
    }
    __syncthreads();

    const int half = tid >> 9;          // 0 = rows, 1 = cols
    const int b    = (tid >> 2) & 127;
    const int q    = tid & 3;           // quarter (32 elements each)

    float mx = -3.0e38f;
    #pragma unroll 8
    for (int j = q * 32; j < q * 32 + 32; j++) {
        float v = (half ? sh[j * 129 + b] : sh[b * 129 + j]) * invT;
        mx = fmaxf(mx, v);
    }
    #pragma unroll
    for (int o = 1; o <= 2; o <<= 1)
        mx = fmaxf(mx, __shfl_xor_sync(0xffffffffu, mx, o));

    float s = 0.0f;
    #pragma unroll 8
    for (int j = q * 32; j < q * 32 + 32; j++) {
        float v = (half ? sh[j * 129 + b] : sh[b * 129 + j]) * invT;
        s += __expf(v - mx);
    }
    #pragma unroll
    for (int o = 1; o <= 2; o <<= 1)
        s += __shfl_xor_sync(0xffffffffu, s, o);

    float part = 0.0f;
    if (q == 0) {
        float lse = mx + __logf(s);
        part = 0.5f * lse;
        if (half == 0) part -= sh[b * 129 + b] * invT;
    }
    #pragma unroll
    for (int o = 16; o >= 1; o >>= 1) part += __shfl_xor_sync(0xffffffffu, part, o);
    if ((tid & 31) == 0) ws[tid >> 5] = part;
    __syncthreads();
    if (tid < 32) {
        float v = ws[tid];
        #pragma unroll
        for (int o = 16; o >= 1; o >>= 1) v += __shfl_xor_sync(0xffffffffu, v, o);
        if (tid == 0) out[0] = v * (1.0f / BB);
    }
}

// ---------------- launch ----------------------------------------------------
extern "C" void kernel_launch(void* const* d_in, const int* in_sizes, int n_in,
                              void* d_out, int out_size)
{
    const float* a0 = (const float*)d_in[0];
    const float* a1 = (const float*)d_in[1];
    const float *img, *txt;
    if (in_sizes[0] == BB * II * DD) { img = a0; txt = a1; }
    else                             { img = a1; txt = a0; }

    cudaFuncSetAttribute(maxsim_mma_kernel,
                         cudaFuncAttributeMaxDynamicSharedMemorySize, SMEM_TOTAL);
    cudaFuncSetAttribute(loss_kernel,
                         cudaFuncAttributeMaxDynamicSharedMemorySize, 129 * 128 * 4);

    __half *th, *ih;
    cudaGetSymbolAddress((void**)&th, g_txt);
    cudaGetSymbolAddress((void**)&ih, g_img);

    const int nt4 = BB * TT * DD / 4;
    const int ni4 = BB * II * DD / 4;
    round2_kernel<<<(nt4 + ni4 + 255) / 256, 256>>>(txt, img, th, ih, nt4, ni4);

    dim3 grid(BB, BB);   // 128 x 128
    maxsim_mma_kernel<<<grid, 128, SMEM_TOTAL>>>();

    loss_kernel<<<1, 1024, 129 * 128 * 4>>>((float*)d_out);
}

// round 14
// speedup vs baseline: 1.0976x; 1.0976x over previous
#include <cuda_runtime.h>
#include <cuda_fp16.h>
#include <cstdint>

#define BB 128
#define TT 64
#define II 196
#define DD 512

// ---------------- scratch --------------------------------------------------
__device__ __align__(16) __half g_txt[BB * TT * DD];
__device__ __align__(16) __half g_img[BB * II * DD];
__device__ float g_S[BB * BB];

// ---------------- stage layout (bytes); K-chunk = 64 halves = 128 B/row ----
// A: 64 rows x 128B = 8192 ; B: 208 rows x 128B = 26624
#define A_T  0
#define B_T  8192
#define STAGE_SZ 34816
#define N_STAGE 3
#define SMEM_TOTAL (N_STAGE * STAGE_SZ + 2048)   // 106496 -> 2 CTAs/SM

// ---------------- PTX helpers ----------------------------------------------
__device__ __forceinline__ uint32_t smem_u32(const void* p) {
    uint32_t a;
    asm("{ .reg .u64 t; cvta.to.shared.u64 t, %1; cvt.u32.u64 %0, t; }"
        : "=r"(a) : "l"(p));
    return a;
}
__device__ __forceinline__ void cp16(uint32_t dst, const void* src) {
    asm volatile("cp.async.cg.shared.global [%0], [%1], 16;"
                 :: "r"(dst), "l"(src) : "memory");
}
#define CP_COMMIT() asm volatile("cp.async.commit_group;" ::: "memory")
#define CP_WAIT2()  asm volatile("cp.async.wait_group 2;" ::: "memory")
#define CP_WAIT1()  asm volatile("cp.async.wait_group 1;" ::: "memory")
#define CP_WAIT0()  asm volatile("cp.async.wait_group 0;" ::: "memory")

__device__ __forceinline__ void ldsm4(uint32_t* r, uint32_t addr) {
    asm volatile("ldmatrix.sync.aligned.m8n8.x4.shared.b16 {%0,%1,%2,%3}, [%4];"
                 : "=r"(r[0]), "=r"(r[1]), "=r"(r[2]), "=r"(r[3]) : "r"(addr));
}
__device__ __forceinline__ void mma_f16(float* c, const uint32_t* a, const uint32_t* b) {
    asm volatile("mma.sync.aligned.m16n8k16.row.col.f32.f16.f16.f32 "
                 "{%0,%1,%2,%3}, {%4,%5,%6,%7}, {%8,%9}, {%0,%1,%2,%3};"
                 : "+f"(c[0]), "+f"(c[1]), "+f"(c[2]), "+f"(c[3])
                 : "r"(a[0]), "r"(a[1]), "r"(a[2]), "r"(a[3]),
                   "r"(b[0]), "r"(b[1]));
}
__device__ __forceinline__ uint32_t swz(int row, uint32_t kb) {
    return (uint32_t)row * 128u + (kb ^ (uint32_t)((row & 7) << 4));
}

// ---------------- fused round kernel: fp32 -> fp16, 2 float4/thread ---------
__device__ __forceinline__ void cvt4(const float4& v, uint2& u) {
    __half2 a(__float2half(v.x), __float2half(v.y));
    __half2 b(__float2half(v.z), __float2half(v.w));
    u.x = *(uint32_t*)&a; u.y = *(uint32_t*)&b;
}

__global__ __launch_bounds__(256)
void round2_kernel(const float* __restrict__ t, const float* __restrict__ im,
                   __half* __restrict__ th, __half* __restrict__ ih,
                   int nt8, int ni8)   // counts of float4-PAIRS per tensor
{
    int i = blockIdx.x * 256 + threadIdx.x;
    const float4* src;
    uint2* dst;
    int j;
    if (i < nt8) { src = (const float4*)t; dst = (uint2*)th; j = i; }
    else         { j = i - nt8; if (j >= ni8) return;
                   src = (const float4*)im; dst = (uint2*)ih; }
    // two independent chains, stride nX8 apart (both in-bounds by construction)
    int stride = (i < nt8) ? nt8 : ni8;
    float4 v0 = src[j];
    float4 v1 = src[j + stride];
    uint2 u0, u1;
    cvt4(v0, u0);
    cvt4(v1, u1);
    dst[j]          = u0;
    dst[j + stride] = u1;
}

// ---------------- stage loader (128 threads) --------------------------------
__device__ __forceinline__ void issue_stage(uint32_t sb,
    const __half* At, const __half* Bt, int k0, int tid)
{
    #pragma unroll
    for (int q = 0; q < 4; q++) {                 // A: 64 rows x 8 segs(16B)
        int u = tid + q * 128;
        int row = u >> 3, seg = u & 7;
        uint32_t o = swz(row, seg * 16);
        size_t g = (size_t)row * DD + k0 + seg * 8;
        cp16(sb + A_T + o, At + g);
    }
    #pragma unroll
    for (int q = 0; q < 13; q++) {                // B: 196 rows x 8 segs = 1568
        int u = tid + q * 128;
        if (u < II * 8) {
            int row = u >> 3, seg = u & 7;
            uint32_t o = swz(row, seg * 16);
            size_t g = (size_t)row * DD + k0 + seg * 8;
            cp16(sb + B_T + o, Bt + g);
        }
    }
}

// ---------------- per-chunk compute: 32x104 warp tile (uniform, R12) --------
__device__ __forceinline__ void compute_chunk(uint32_t sb, float* c,
                                              int wr, int wc, int lane)
{
    const int rowA0 = wr * 32 + (lane & 15);
    const uint32_t kAh = (lane & 16) ? 16u : 0u;
    const int rowB0 = wc * 104 + ((lane & 16) ? 8 : 0) + (lane & 7);
    const uint32_t kBh = (lane & 8) ? 16u : 0u;

    #pragma unroll
    for (int s = 0; s < 4; s++) {
        uint32_t a[8];
        #pragma unroll
        for (int mt = 0; mt < 2; mt++) {
            uint32_t o = swz(rowA0 + mt * 16, s * 32 + kAh);
            ldsm4(a + 4 * mt, sb + A_T + o);
        }
        uint32_t b[28];
        #pragma unroll
        for (int p = 0; p < 7; p++) {             // covers 14 n8-tiles; use 13
            uint32_t o = swz(rowB0 + p * 16, s * 32 + kBh);
            ldsm4(b + 4 * p, sb + B_T + o);
        }
        #pragma unroll
        for (int mt = 0; mt < 2; mt++)
            #pragma unroll
            for (int nt = 0; nt < 13; nt++)
                mma_f16(c + (mt * 13 + nt) * 4, a + 4 * mt, b + 2 * nt);
    }
}

// ---------------- main maxsim kernel ----------------------------------------
__global__ __launch_bounds__(128, 2)
void maxsim_mma_kernel()
{
    extern __shared__ __align__(1024) char smem[];
    const uint32_t sb = smem_u32(smem);
    const int tid  = threadIdx.x;
    const int lane = tid & 31;
    const int wid  = tid >> 5;
    const int wr   = wid >> 1;      // 0..1 : M strip of 32
    const int wc   = wid & 1;       // 0..1 : N strip of 104

    const int b1 = blockIdx.x;      // text batch
    const int b2 = blockIdx.y;      // image batch
    const __half* At = g_txt + (size_t)b1 * (TT * DD);
    const __half* Bt = g_img + (size_t)b2 * (II * DD);

    // zero B pad rows (196..207) in all stages
    {
        uint4 z = make_uint4(0, 0, 0, 0);
        for (int u = tid; u < 12 * 8 * N_STAGE; u += 128) {
            int st = u / 96, v = u % 96;
            int row = 196 + (v >> 3), seg = v & 7;
            uint32_t o = swz(row, seg * 16);
            *(uint4*)(smem + st * STAGE_SZ + B_T + o) = z;
        }
    }
    __syncthreads();

    issue_stage(sb,                At, Bt, 0,   tid); CP_COMMIT();
    issue_stage(sb + STAGE_SZ,     At, Bt, 64,  tid); CP_COMMIT();
    issue_stage(sb + 2 * STAGE_SZ, At, Bt, 128, tid); CP_COMMIT();

    float c[104];
    #pragma unroll
    for (int i = 0; i < 104; i++) c[i] = 0.0f;

    #pragma unroll 1
    for (int ck = 0; ck < 8; ck++) {
        if (ck < 6) CP_WAIT2();
        else if (ck == 6) CP_WAIT1();
        else CP_WAIT0();
        __syncthreads();
        const uint32_t stg = sb + (uint32_t)(ck % 3) * STAGE_SZ;
        compute_chunk(stg, c, wr, wc, lane);
        __syncthreads();
        if (ck + 3 <= 7) {
            issue_stage(stg, At, Bt, (ck + 3) * 64, tid);
            CP_COMMIT();
        }
    }

    // ---------------- epilogue: masked row-max, then mean over tokens -------
    float* red = (float*)smem;      // [2][64] then [64] scratch
    #pragma unroll
    for (int mt = 0; mt < 2; mt++) {
        float m0 = -3.0e38f, m1 = -3.0e38f;
        #pragma unroll
        for (int nt = 0; nt < 13; nt++) {
            const float* acc = c + (mt * 13 + nt) * 4;
            int i0 = wc * 104 + nt * 8 + 2 * (lane & 3);
            if (i0 < II)     { m0 = fmaxf(m0, acc[0]); m1 = fmaxf(m1, acc[2]); }
            if (i0 + 1 < II) { m0 = fmaxf(m0, acc[1]); m1 = fmaxf(m1, acc[3]); }
        }
        #pragma unroll
        for (int o = 1; o <= 2; o <<= 1) {
            m0 = fmaxf(m0, __shfl_xor_sync(0xffffffffu, m0, o));
            m1 = fmaxf(m1, __shfl_xor_sync(0xffffffffu, m1, o));
        }
        if ((lane & 3) == 0) {
            int t = wr * 32 + mt * 16 + (lane >> 2);
            red[wc * 64 + t]     = m0;
            red[wc * 64 + t + 8] = m1;
        }
    }
    __syncthreads();
    float* red2 = red + 128;
    if (tid < 64) red2[tid] = fmaxf(red[tid], red[64 + tid]);
    __syncthreads();
    if (wid == 0) {
        float v = red2[lane] + red2[lane + 32];
        #pragma unroll
        for (int o = 16; o >= 1; o >>= 1) v += __shfl_xor_sync(0xffffffffu, v, o);
        if (lane == 0) g_S[b1 * BB + b2] = v * (1.0f / 64.0f);
    }
}

// ---------------- loss kernel (1024 thr; 4 lanes per row/col) ---------------
__global__ __launch_bounds__(1024)
void loss_kernel(float* __restrict__ out)
{
    extern __shared__ float sh[];                 // [128][129]
    __shared__ float ws[32];
    const int tid = threadIdx.x;
    const float invT = 1.0f / 0.07f;

    for (int i = tid; i < BB * 32; i += 1024) {
        int b = i >> 5, j4 = i & 31;
        float4 v = reinterpret_cast<const float4*>(g_S)[b * 32 + j4];
        float* row = sh + b * 129 + j4 * 4;
        row[0] = v.x; row[1] = v.y; row[2] = v.z; row[3] = v.w;
    }
    __syncthreads();

    const int half = tid >> 9;          // 0 = rows, 1 = cols
    const int b    = (tid >> 2) & 127;
    const int q    = tid & 3;           // quarter (32 elements each)

    float mx = -3.0e38f;
    #pragma unroll 8
    for (int j = q * 32; j < q * 32 + 32; j++) {
        float v = (half ? sh[j * 129 + b] : sh[b * 129 + j]) * invT;
        mx = fmaxf(mx, v);
    }
    #pragma unroll
    for (int o = 1; o <= 2; o <<= 1)
        mx = fmaxf(mx, __shfl_xor_sync(0xffffffffu, mx, o));

    float s = 0.0f;
    #pragma unroll 8
    for (int j = q * 32; j < q * 32 + 32; j++) {
        float v = (half ? sh[j * 129 + b] : sh[b * 129 + j]) * invT;
        s += __expf(v - mx);
    }
    #pragma unroll
    for (int o = 1; o <= 2; o <<= 1)
        s += __shfl_xor_sync(0xffffffffu, s, o);

    float part = 0.0f;
    if (q == 0) {
        float lse = mx + __logf(s);
        part = 0.5f * lse;
        if (half == 0) part -= sh[b * 129 + b] * invT;
    }
    #pragma unroll
    for (int o = 16; o >= 1; o >>= 1) part += __shfl_xor_sync(0xffffffffu, part, o);
    if ((tid & 31) == 0) ws[tid >> 5] = part;
    __syncthreads();
    if (tid < 32) {
        float v = ws[tid];
        #pragma unroll
        for (int o = 16; o >= 1; o >>= 1) v += __shfl_xor_sync(0xffffffffu, v, o);
        if (tid == 0) out[0] = v * (1.0f / BB);
    }
}

// ---------------- launch ----------------------------------------------------
extern "C" void kernel_launch(void* const* d_in, const int* in_sizes, int n_in,
                              void* d_out, int out_size)
{
    const float* a0 = (const float*)d_in[0];
    const float* a1 = (const float*)d_in[1];
    const float *img, *txt;
    if (in_sizes[0] == BB * II * DD) { img = a0; txt = a1; }
    else                             { img = a1; txt = a0; }

    cudaFuncSetAttribute(maxsim_mma_kernel,
                         cudaFuncAttributeMaxDynamicSharedMemorySize, SMEM_TOTAL);
    cudaFuncSetAttribute(loss_kernel,
                         cudaFuncAttributeMaxDynamicSharedMemorySize, 129 * 128 * 4);

    __half *th, *ih;
    cudaGetSymbolAddress((void**)&th, g_txt);
    cudaGetSymbolAddress((void**)&ih, g_img);

    const int nt8 = BB * TT * DD / 8;   // float4 pairs in text
    const int ni8 = BB * II * DD / 8;   // float4 pairs in image
    round2_kernel<<<(nt8 + ni8 + 255) / 256, 256>>>(txt, img, th, ih, nt8, ni8);

    dim3 grid(BB, BB);   // 128 x 128
    maxsim_mma_kernel<<<grid, 128, SMEM_TOTAL>>>();

    loss_kernel<<<1, 1024, 129 * 128 * 4>>>((float*)d_out);
}

// round 15
// speedup vs baseline: 1.1332x; 1.0325x over previous
#include <cuda_runtime.h>
#include <cuda_fp16.h>
#include <cstdint>

#define BB 128
#define TT 64
#define II 196
#define DD 512

// ---------------- scratch --------------------------------------------------
__device__ __align__(16) __half g_txt[BB * TT * DD];
__device__ __align__(16) __half g_img[BB * II * DD];
__device__ float g_S[BB * BB];

// ---------------- stage layout (bytes); K-chunk = 64 halves = 128 B/row ----
// A: 64 rows x 128B = 8192 ; B: 208 rows x 128B = 26624
#define A_T  0
#define B_T  8192
#define STAGE_SZ 34816
#define N_STAGE 3
#define SMEM_TOTAL (N_STAGE * STAGE_SZ + 2048)   // 106496 -> 2 CTAs/SM

// ---------------- PTX helpers ----------------------------------------------
__device__ __forceinline__ uint32_t smem_u32(const void* p) {
    uint32_t a;
    asm("{ .reg .u64 t; cvta.to.shared.u64 t, %1; cvt.u32.u64 %0, t; }"
        : "=r"(a) : "l"(p));
    return a;
}
__device__ __forceinline__ void cp16(uint32_t dst, const void* src) {
    asm volatile("cp.async.cg.shared.global [%0], [%1], 16;"
                 :: "r"(dst), "l"(src) : "memory");
}
#define CP_COMMIT() asm volatile("cp.async.commit_group;" ::: "memory")
#define CP_WAIT1()  asm volatile("cp.async.wait_group 1;" ::: "memory")
#define CP_WAIT0()  asm volatile("cp.async.wait_group 0;" ::: "memory")

__device__ __forceinline__ void ldsm4(uint32_t* r, uint32_t addr) {
    asm volatile("ldmatrix.sync.aligned.m8n8.x4.shared.b16 {%0,%1,%2,%3}, [%4];"
                 : "=r"(r[0]), "=r"(r[1]), "=r"(r[2]), "=r"(r[3]) : "r"(addr));
}
__device__ __forceinline__ void mma_f16(float* c, const uint32_t* a, const uint32_t* b) {
    asm volatile("mma.sync.aligned.m16n8k16.row.col.f32.f16.f16.f32 "
                 "{%0,%1,%2,%3}, {%4,%5,%6,%7}, {%8,%9}, {%0,%1,%2,%3};"
                 : "+f"(c[0]), "+f"(c[1]), "+f"(c[2]), "+f"(c[3])
                 : "r"(a[0]), "r"(a[1]), "r"(a[2]), "r"(a[3]),
                   "r"(b[0]), "r"(b[1]));
}
__device__ __forceinline__ uint32_t swz(int row, uint32_t kb) {
    return (uint32_t)row * 128u + (kb ^ (uint32_t)((row & 7) << 4));
}

// ---------------- fused round kernel: fp32 -> fp16, 2 float4/thread ---------
__device__ __forceinline__ void cvt4(const float4& v, uint2& u) {
    __half2 a(__float2half(v.x), __float2half(v.y));
    __half2 b(__float2half(v.z), __float2half(v.w));
    u.x = *(uint32_t*)&a; u.y = *(uint32_t*)&b;
}

__global__ __launch_bounds__(256)
void round2_kernel(const float* __restrict__ t, const float* __restrict__ im,
                   __half* __restrict__ th, __half* __restrict__ ih,
                   int nt8, int ni8)   // counts of float4-PAIRS per tensor
{
    int i = blockIdx.x * 256 + threadIdx.x;
    const float4* src;
    uint2* dst;
    int j;
    if (i < nt8) { src = (const float4*)t; dst = (uint2*)th; j = i; }
    else         { j = i - nt8; if (j >= ni8) return;
                   src = (const float4*)im; dst = (uint2*)ih; }
    int stride = (i < nt8) ? nt8 : ni8;
    float4 v0 = src[j];
    float4 v1 = src[j + stride];
    uint2 u0, u1;
    cvt4(v0, u0);
    cvt4(v1, u1);
    dst[j]          = u0;
    dst[j + stride] = u1;
}

// ---------------- stage loader (128 threads) --------------------------------
__device__ __forceinline__ void issue_stage(uint32_t sb,
    const __half* At, const __half* Bt, int k0, int tid)
{
    #pragma unroll
    for (int q = 0; q < 4; q++) {                 // A: 64 rows x 8 segs(16B)
        int u = tid + q * 128;
        int row = u >> 3, seg = u & 7;
        uint32_t o = swz(row, seg * 16);
        size_t g = (size_t)row * DD + k0 + seg * 8;
        cp16(sb + A_T + o, At + g);
    }
    #pragma unroll
    for (int q = 0; q < 13; q++) {                // B: 196 rows x 8 segs = 1568
        int u = tid + q * 128;
        if (u < II * 8) {
            int row = u >> 3, seg = u & 7;
            uint32_t o = swz(row, seg * 16);
            size_t g = (size_t)row * DD + k0 + seg * 8;
            cp16(sb + B_T + o, Bt + g);
        }
    }
}

// ---------------- per-chunk compute: 32x104 warp tile (uniform, R12) --------
__device__ __forceinline__ void compute_chunk(uint32_t sb, float* c,
                                              int wr, int wc, int lane)
{
    const int rowA0 = wr * 32 + (lane & 15);
    const uint32_t kAh = (lane & 16) ? 16u : 0u;
    const int rowB0 = wc * 104 + ((lane & 16) ? 8 : 0) + (lane & 7);
    const uint32_t kBh = (lane & 8) ? 16u : 0u;

    #pragma unroll
    for (int s = 0; s < 4; s++) {
        uint32_t a[8];
        #pragma unroll
        for (int mt = 0; mt < 2; mt++) {
            uint32_t o = swz(rowA0 + mt * 16, s * 32 + kAh);
            ldsm4(a + 4 * mt, sb + A_T + o);
        }
        uint32_t b[28];
        #pragma unroll
        for (int p = 0; p < 7; p++) {             // covers 14 n8-tiles; use 13
            uint32_t o = swz(rowB0 + p * 16, s * 32 + kBh);
            ldsm4(b + 4 * p, sb + B_T + o);
        }
        #pragma unroll
        for (int mt = 0; mt < 2; mt++)
            #pragma unroll
            for (int nt = 0; nt < 13; nt++)
                mma_f16(c + (mt * 13 + nt) * 4, a + 4 * mt, b + 2 * nt);
    }
}

// ---------------- main maxsim kernel ----------------------------------------
__global__ __launch_bounds__(128, 2)
void maxsim_mma_kernel()
{
    extern __shared__ __align__(1024) char smem[];
    const uint32_t sb = smem_u32(smem);
    const int tid  = threadIdx.x;
    const int lane = tid & 31;
    const int wid  = tid >> 5;
    const int wr   = wid >> 1;      // 0..1 : M strip of 32
    const int wc   = wid & 1;       // 0..1 : N strip of 104

    const int b1 = blockIdx.x;      // text batch
    const int b2 = blockIdx.y;      // image batch
    const __half* At = g_txt + (size_t)b1 * (TT * DD);
    const __half* Bt = g_img + (size_t)b2 * (II * DD);

    // zero B pad rows (196..207) in all stages
    {
        uint4 z = make_uint4(0, 0, 0, 0);
        for (int u = tid; u < 12 * 8 * N_STAGE; u += 128) {
            int st = u / 96, v = u % 96;
            int row = 196 + (v >> 3), seg = v & 7;
            uint32_t o = swz(row, seg * 16);
            *(uint4*)(smem + st * STAGE_SZ + B_T + o) = z;
        }
    }
    __syncthreads();

    // prime 2 chunks (depth-2 prefetch, 3 stages)
    issue_stage(sb,            At, Bt, 0,  tid); CP_COMMIT();
    issue_stage(sb + STAGE_SZ, At, Bt, 64, tid); CP_COMMIT();

    float c[104];
    #pragma unroll
    for (int i = 0; i < 104; i++) c[i] = 0.0f;

    // ONE barrier per chunk: at top of iter ck, stage (ck+2)%3 == (ck-1)%3
    // was fully consumed in iter ck-1 (proven by this barrier), so the new
    // issue targets it safely.
    #pragma unroll 1
    for (int ck = 0; ck < 8; ck++) {
        if (ck < 7) CP_WAIT1(); else CP_WAIT0();
        __syncthreads();
        if (ck + 2 <= 7) {
            issue_stage(sb + (uint32_t)((ck + 2) % 3) * STAGE_SZ,
                        At, Bt, (ck + 2) * 64, tid);
            CP_COMMIT();
        }
        compute_chunk(sb + (uint32_t)(ck % 3) * STAGE_SZ, c, wr, wc, lane);
    }

    // ---------------- epilogue: masked row-max, then mean over tokens -------
    __syncthreads();                 // all compute done before smem reuse
    float* red = (float*)smem;       // [2][64] then [64] scratch
    #pragma unroll
    for (int mt = 0; mt < 2; mt++) {
        float m0 = -3.0e38f, m1 = -3.0e38f;
        #pragma unroll
        for (int nt = 0; nt < 13; nt++) {
            const float* acc = c + (mt * 13 + nt) * 4;
            int i0 = wc * 104 + nt * 8 + 2 * (lane & 3);
            if (i0 < II)     { m0 = fmaxf(m0, acc[0]); m1 = fmaxf(m1, acc[2]); }
            if (i0 + 1 < II) { m0 = fmaxf(m0, acc[1]); m1 = fmaxf(m1, acc[3]); }
        }
        #pragma unroll
        for (int o = 1; o <= 2; o <<= 1) {
            m0 = fmaxf(m0, __shfl_xor_sync(0xffffffffu, m0, o));
            m1 = fmaxf(m1, __shfl_xor_sync(0xffffffffu, m1, o));
        }
        if ((lane & 3) == 0) {
            int t = wr * 32 + mt * 16 + (lane >> 2);
            red[wc * 64 + t]     = m0;
            red[wc * 64 + t + 8] = m1;
        }
    }
    __syncthreads();
    float* red2 = red + 128;
    if (tid < 64) red2[tid] = fmaxf(red[tid], red[64 + tid]);
    __syncthreads();
    if (wid == 0) {
        float v = red2[lane] + red2[lane + 32];
        #pragma unroll
        for (int o = 16; o >= 1; o >>= 1) v += __shfl_xor_sync(0xffffffffu, v, o);
        if (lane == 0) g_S[b1 * BB + b2] = v * (1.0f / 64.0f);
    }
}

// ---------------- loss kernel (1024 thr; 4 lanes per row/col) ---------------
__global__ __launch_bounds__(1024)
void loss_kernel(float* __restrict__ out)
{
    extern __shared__ float sh[];                 // [128][129]
    __shared__ float ws[32];
    const int tid = threadIdx.x;
    const float invT = 1.0f / 0.07f;

    for (int i = tid; i < BB * 32; i += 1024) {
        int b = i >> 5, j4 = i & 31;
        float4 v = reinterpret_cast<const float4*>(g_S)[b * 32 + j4];
        float* row = sh + b * 129 + j4 * 4;
        row[0] = v.x; row[1] = v.y; row[2] = v.z; row[3] = v.w;
    }
    __syncthreads();

    const int half = tid >> 9;          // 0 = rows, 1 = cols
    const int b    = (tid >> 2) & 127;
    const int q    = tid & 3;           // quarter (32 elements each)

    float mx = -3.0e38f;
    #pragma unroll 8
    for (int j = q * 32; j < q * 32 + 32; j++) {
        float v = (half ? sh[j * 129 + b] : sh[b * 129 + j]) * invT;
        mx = fmaxf(mx, v);
    }
    #pragma unroll
    for (int o = 1; o <= 2; o <<= 1)
        mx = fmaxf(mx, __shfl_xor_sync(0xffffffffu, mx, o));

    float s = 0.0f;
    #pragma unroll 8
    for (int j = q * 32; j < q * 32 + 32; j++) {
        float v = (half ? sh[j * 129 + b] : sh[b * 129 + j]) * invT;
        s += __expf(v - mx);
    }
    #pragma unroll
    for (int o = 1; o <= 2; o <<= 1)
        s += __shfl_xor_sync(0xffffffffu, s, o);

    float part = 0.0f;
    if (q == 0) {
        float lse = mx + __logf(s);
        part = 0.5f * lse;
        if (half == 0) part -= sh[b * 129 + b] * invT;
    }
    #pragma unroll
    for (int o = 16; o >= 1; o >>= 1) part += __shfl_xor_sync(0xffffffffu, part, o);
    if ((tid & 31) == 0) ws[tid >> 5] = part;
    __syncthreads();
    if (tid < 32) {
        float v = ws[tid];
        #pragma unroll
        for (int o = 16; o >= 1; o >>= 1) v += __shfl_xor_sync(0xffffffffu, v, o);
        if (tid == 0) out[0] = v * (1.0f / BB);
    }
}

// ---------------- launch ----------------------------------------------------
extern "C" void kernel_launch(void* const* d_in, const int* in_sizes, int n_in,
                              void* d_out, int out_size)
{
    const float* a0 = (const float*)d_in[0];
    const float* a1 = (const float*)d_in[1];
    const float *img, *txt;
    if (in_sizes[0] == BB * II * DD) { img = a0; txt = a1; }
    else                             { img = a1; txt = a0; }

    cudaFuncSetAttribute(maxsim_mma_kernel,
                         cudaFuncAttributeMaxDynamicSharedMemorySize, SMEM_TOTAL);
    cudaFuncSetAttribute(loss_kernel,
                         cudaFuncAttributeMaxDynamicSharedMemorySize, 129 * 128 * 4);

    __half *th, *ih;
    cudaGetSymbolAddress((void**)&th, g_txt);
    cudaGetSymbolAddress((void**)&ih, g_img);

    const int nt8 = BB * TT * DD / 8;   // float4 pairs in text
    const int ni8 = BB * II * DD / 8;   // float4 pairs in image
    round2_kernel<<<(nt8 + ni8 + 255) / 256, 256>>>(txt, img, th, ih, nt8, ni8);

    dim3 grid(BB, BB);   // 128 x 128
    maxsim_mma_kernel<<<grid, 128, SMEM_TOTAL>>>();

    loss_kernel<<<1, 1024, 129 * 128 * 4>>>((float*)d_out);
}